// round 16
// baseline (speedup 1.0000x reference)
#include <cuda_runtime.h>
#include <math.h>
#include <stdint.h>

#define BN 64
#define CN 512
#define HW 784
#define HW4 196
#define R_TOT (BN * CN)
#define FEPS 1e-12f

#define ROWB 3136                  // bytes per A row
#define DEPTH 2                    // cp.async stages per warp
#define SM_PIPE (8 * DEPTH * ROWB) // 50176
#define SM_YS   SM_PIPE            // ys: 784 floats
#define SM_TOTAL (SM_YS + HW * 4 + 64)

#define WSTRIDE_F (DEPTH * ROWB / 4 + 8)   // 1576 floats: warp slot + bank skew

// ---------------- scratch (static __device__, no allocation) ----------------
__device__ __align__(16) float g_Y[6][BN * HW];  // summed W^T z per sweep
__device__ float g_u4[BN * CN];
__device__ float g_nrm[6][BN];            // 0:||x0||^2 1..4:||z_k||^2 5:||w||^2
__device__ float g_pen[BN];
__device__ int   g_pendone;

__device__ __forceinline__ uint32_t s2u(const void* p) {
    uint32_t a;
    asm("{.reg .u64 t; cvta.to.shared.u64 t, %1; cvt.u32.u64 %0, t;}" : "=r"(a) : "l"(p));
    return a;
}
// Plain cp.async (LDGSTS); the cache-hint form traps on sm_103a.
__device__ __forceinline__ void cpa16(uint32_t dst, const float4* src) {
    asm volatile("cp.async.cg.shared.global [%0], [%1], 16;"
                 :: "r"(dst), "l"(src) : "memory");
}
#define CPA_COMMIT() asm volatile("cp.async.commit_group;" ::: "memory")
#define CPA_WAIT1()  asm volatile("cp.async.wait_group 1;" ::: "memory")
#define CPA_WAIT0()  asm volatile("cp.async.wait_group 0;" ::: "memory")
__device__ __forceinline__ float ldcg(const float* p) {
    float v; asm volatile("ld.global.cg.f32 %0,[%1];" : "=f"(v) : "l"(p)); return v;
}

// ---------------- init: zero Y+accums, ||x0||^2 ----------------
__global__ void k_init0(const float* __restrict__ x0) {
    __shared__ float red[16];
    int b = blockIdx.x, t = threadIdx.x;       // 64 blocks x 512 threads
    for (int s = 0; s < 6; s++)
        for (int i = t; i < HW; i += 512) g_Y[s][b * HW + i] = 0.f;
    if (t < 6) g_nrm[t][b] = 0.0f;
    if (b == 0 && t == 0) g_pendone = 0;
    float v = x0[b * CN + t];
    float s = v * v;
    #pragma unroll
    for (int o = 16; o; o >>= 1) s += __shfl_xor_sync(0xffffffffu, s, o);
    if ((t & 31) == 0) red[t >> 5] = s;
    __syncthreads();
    if (t < 16) {
        s = red[t];
        #pragma unroll
        for (int o = 8; o; o >>= 1) s += __shfl_xor_sync(0xffffu, s, o);
        if (t == 0) g_nrm[0][b] = s;
    }
}

// ---------------- sweep kernel: cp.async-fed, 3 CTAs/SM ---------------------
// SWEEP 0: z = x0[c] (axpy only)
// SWEEP 1..4: z = A_row . ys (ys = Y[S-1]*rsqrt(nrm[S-1])); ||z||^2 -> nrm[S];
//             SWEEP 4 stores z -> g_u4
// SWEEP 5: largest/inv4 block-computed during ys build;
//          ys = Y4*inv4; w = z - largest*(u4*inv4); ||w||^2 -> nrm[5]
template<int SWEEP>
__global__ void __launch_bounds__(256, 3) k_ap(
        const float4* __restrict__ A4, const float* __restrict__ x0, int G)
{
    extern __shared__ char sm[];
    float* smf = (float*)sm;
    float* ys = (float*)(sm + SM_YS);
    const float4* ys4 = (const float4*)ys;
    __shared__ float r1s[8];
    __shared__ float sh_lg;
    int t = threadIdx.x, warp = t >> 5, lane = t & 31;   // 256 threads
    bool k6 = (lane < 4);
    uint32_t pbase = s2u(sm) + warp * (DEPTH * ROWB) + lane * 16;
    const float4* pipe4 = (const float4*)(sm + warp * (DEPTH * ROWB));

    int rs = (int)((long long)blockIdx.x * R_TOT / G);
    int re = (int)((long long)(blockIdx.x + 1) * R_TOT / G);

    bool first = true;
    while (rs < re) {
        int b = rs >> 9;
        int cs = rs & (CN - 1);
        int ce = re - (b << 9); if (ce > CN) ce = CN;

        if (!first) __syncthreads();   // protect ys/pipe reuse across subranges
        first = false;

        // ---- cooperative ys build in shared; sweep5 also largest ----
        float largest = 0.f, inv4 = 1.f;
        if (SWEEP >= 1) {
            int ssrc = (SWEEP <= 4) ? SWEEP - 1 : 4;
            const float* Ysrc = &g_Y[ssrc][b * HW];
            float sc = 1.0f / fmaxf(sqrtf(g_nrm[ssrc][b]), FEPS);
            if (SWEEP < 5) {
                for (int i = t; i < HW; i += 256) ys[i] = __ldg(Ysrc + i) * sc;
            } else {
                inv4 = sc;
                float sq = 0.f;
                for (int i = t; i < HW; i += 256) {
                    float y = __ldg(Ysrc + i);
                    sq += y * y;
                    ys[i] = y * sc;
                }
                #pragma unroll
                for (int o = 16; o; o >>= 1) sq += __shfl_xor_sync(0xffffffffu, sq, o);
                if (lane == 0) r1s[warp] = sq;
                __syncthreads();
                if (t == 0) {
                    float tot = 0.f;
                    #pragma unroll
                    for (int w = 0; w < 8; w++) tot += r1s[w];
                    sh_lg = tot * sc * sc;    // largest = ||W^T x1||^2
                }
            }
        }
        __syncthreads();
        if (SWEEP == 5) largest = sh_lg;

        float4 acc[7];
        #pragma unroll
        for (int k = 0; k < 7; k++) acc[k] = make_float4(0.f, 0.f, 0.f, 0.f);
        float la1 = 0.f;

        // ---- per-warp cp.async pipeline over rows c = cs+warp, step 8 ----
        int c0 = cs + warp;
        #pragma unroll
        for (int d = 0; d < DEPTH; d++) {
            int c = c0 + d * 8;
            if (c < ce) {
                const float4* src = A4 + (size_t)(b * CN + c) * HW4;
                uint32_t dst = pbase + d * ROWB;
                #pragma unroll
                for (int k = 0; k < 6; k++) cpa16(dst + k * 512, src + k * 32 + lane);
                if (k6) cpa16(dst + 6 * 512, src + 192 + lane);
            }
            CPA_COMMIT();
        }

        int stage = 0;
        for (int c = c0; c < ce; c += 8) {
            CPA_WAIT1();   // oldest group (this row) complete
            const float4* Ar = pipe4 + stage * (ROWB / 16);
            float4 a[7];
            #pragma unroll
            for (int k = 0; k < 6; k++) a[k] = Ar[k * 32 + lane];
            a[6] = k6 ? Ar[192 + lane] : make_float4(0.f, 0.f, 0.f, 0.f);

            {
                int cn = c + DEPTH * 8;
                if (cn < ce) {
                    const float4* src = A4 + (size_t)(b * CN + cn) * HW4;
                    uint32_t dst = pbase + stage * ROWB;
                    #pragma unroll
                    for (int k = 0; k < 6; k++) cpa16(dst + k * 512, src + k * 32 + lane);
                    if (k6) cpa16(dst + 6 * 512, src + 192 + lane);
                }
                CPA_COMMIT();
            }

            float z;
            if (SWEEP == 0) {
                z = __ldg(&x0[b * CN + c]);
            } else {
                float d0 = 0.f, d1 = 0.f, d2 = 0.f, d3 = 0.f;
                #pragma unroll
                for (int k = 0; k < 6; k++) {
                    float4 y = ys4[k * 32 + lane];
                    d0 += a[k].x * y.x; d1 += a[k].y * y.y;
                    d2 += a[k].z * y.z; d3 += a[k].w * y.w;
                }
                if (k6) {
                    float4 y = ys4[192 + lane];
                    d0 += a[6].x * y.x; d1 += a[6].y * y.y;
                    d2 += a[6].z * y.z; d3 += a[6].w * y.w;
                }
                z = (d0 + d1) + (d2 + d3);
                #pragma unroll
                for (int o = 16; o; o >>= 1) z += __shfl_xor_sync(0xffffffffu, z, o);
            }
            #pragma unroll
            for (int k = 0; k < 7; k++) {
                acc[k].x += z * a[k].x; acc[k].y += z * a[k].y;
                acc[k].z += z * a[k].z; acc[k].w += z * a[k].w;
            }
            if (lane == 0) {
                if (SWEEP >= 1 && SWEEP <= 4) {
                    if (SWEEP == 4) g_u4[b * CN + c] = z;
                    la1 += z * z;
                } else if (SWEEP == 5) {
                    float wv = z - largest * (g_u4[b * CN + c] * inv4);
                    la1 += wv * wv;
                }
            }
            stage ^= 1;
        }
        CPA_WAIT0();   // own pipe region drained -> reuse as reduce buffer

        // ---- warp accs -> own pipe slot (bank-skewed); block-reduce ----
        {
            float4* yo = (float4*)(smf + warp * WSTRIDE_F);
            #pragma unroll
            for (int k = 0; k < 6; k++) yo[k * 32 + lane] = acc[k];
            if (k6) yo[192 + lane] = acc[6];
            if (lane == 0) r1s[warp] = la1;
        }
        __syncthreads();
        {
            float* Yp = &g_Y[SWEEP][b * HW];
            for (int i = t; i < HW; i += 256) {
                float s = 0.f;
                #pragma unroll
                for (int w = 0; w < 8; w++) s += smf[w * WSTRIDE_F + i];
                atomicAdd(&Yp[i], s);
            }
        }
        if (t == 0 && SWEEP >= 1) {
            float s1 = 0.f;
            #pragma unroll
            for (int w = 0; w < 8; w++) s1 += r1s[w];
            atomicAdd(&g_nrm[SWEEP][b], s1);
        }
        rs = (b << 9) + ce;
    }
}

// ---------------- pen+sum: per-batch penalty; last block sums ----------------
__global__ void k_pensum(float* __restrict__ out) {
    __shared__ int is_last;
    int b = blockIdx.x, t = threadIdx.x, lane = t & 31;   // 64 blocks x 32 thr
    bool k6 = (lane < 4);
    const float4* Y4 = (const float4*)(&g_Y[4][b * HW]);
    const float4* Y5 = (const float4*)(&g_Y[5][b * HW]);
    float inv4 = 1.0f / fmaxf(sqrtf(g_nrm[4][b]), FEPS);
    float s0 = 0.f, s1 = 0.f, s2 = 0.f, s3 = 0.f;
    float4 y4r[7];
    #pragma unroll
    for (int k = 0; k < 6; k++) {
        float4 y = __ldg(Y4 + k * 32 + lane);
        s0 += y.x * y.x; s1 += y.y * y.y;
        s2 += y.z * y.z; s3 += y.w * y.w;
        y4r[k] = y;
    }
    if (k6) {
        float4 y = __ldg(Y4 + 192 + lane);
        s0 += y.x * y.x; s1 += y.y * y.y;
        s2 += y.z * y.z; s3 += y.w * y.w;
        y4r[6] = y;
    } else y4r[6] = make_float4(0.f, 0.f, 0.f, 0.f);
    float sq = (s0 + s1) + (s2 + s3);
    #pragma unroll
    for (int o = 16; o; o >>= 1) sq += __shfl_xor_sync(0xffffffffu, sq, o);
    float largest = sq * inv4 * inv4;
    float f = largest * inv4;
    float n0 = 0.f, n1 = 0.f, n2 = 0.f, n3 = 0.f;
    #pragma unroll
    for (int k = 0; k < 6; k++) {
        float4 y5 = __ldg(Y5 + k * 32 + lane);
        float ex = y5.x - f * y4r[k].x, ey = y5.y - f * y4r[k].y;
        float ez = y5.z - f * y4r[k].z, ew = y5.w - f * y4r[k].w;
        n0 += ex * ex; n1 += ey * ey; n2 += ez * ez; n3 += ew * ew;
    }
    if (k6) {
        float4 y5 = __ldg(Y5 + 192 + lane);
        float ex = y5.x - f * y4r[6].x, ey = y5.y - f * y4r[6].y;
        float ez = y5.z - f * y4r[6].z, ew = y5.w - f * y4r[6].w;
        n0 += ex * ex; n1 += ey * ey; n2 += ez * ez; n3 += ew * ew;
    }
    float num6 = (n0 + n1) + (n2 + n3);
    #pragma unroll
    for (int o = 16; o; o >>= 1) num6 += __shfl_xor_sync(0xffffffffu, num6, o);
    if (t == 0) {
        float smallest = num6 / g_nrm[5][b];     // ||W^T w||^2 / ||w||^2
        float r = largest / smallest - 1.0f;
        g_pen[b] = r * r;
        __threadfence();
        int done = atomicAdd(&g_pendone, 1);
        is_last = (done == BN - 1);
    }
    __syncwarp();
    if (is_last) {
        float p = ldcg(&g_pen[lane]) + ldcg(&g_pen[lane + 32]);
        #pragma unroll
        for (int o = 16; o; o >>= 1) p += __shfl_xor_sync(0xffffffffu, p, o);
        if (t == 0) out[0] = p / (float)BN;
    }
}

// ---------------- launch ----------------
extern "C" void kernel_launch(void* const* d_in, const int* in_sizes, int n_in,
                              void* d_out, int out_size) {
    const float* A  = (const float*)d_in[0];
    const float* x0 = (const float*)d_in[1];
    if (n_in >= 2 && in_sizes[0] < in_sizes[1]) {   // safety: A is the big one
        const float* t = A; A = x0; x0 = t;
    }
    const float4* A4 = (const float4*)A;
    float* out = (float*)d_out;
    (void)out_size;

    cudaFuncSetAttribute(k_ap<0>, cudaFuncAttributeMaxDynamicSharedMemorySize, SM_TOTAL);
    cudaFuncSetAttribute(k_ap<1>, cudaFuncAttributeMaxDynamicSharedMemorySize, SM_TOTAL);
    cudaFuncSetAttribute(k_ap<2>, cudaFuncAttributeMaxDynamicSharedMemorySize, SM_TOTAL);
    cudaFuncSetAttribute(k_ap<3>, cudaFuncAttributeMaxDynamicSharedMemorySize, SM_TOTAL);
    cudaFuncSetAttribute(k_ap<4>, cudaFuncAttributeMaxDynamicSharedMemorySize, SM_TOTAL);
    cudaFuncSetAttribute(k_ap<5>, cudaFuncAttributeMaxDynamicSharedMemorySize, SM_TOTAL);

    int nsm = 148;
    cudaDeviceGetAttribute(&nsm, cudaDevAttrMultiProcessorCount, 0);
    int G = nsm * 3;                         // exactly-resident balanced grid

    k_init0<<<BN, 512>>>(x0);

    k_ap<0><<<G, 256, SM_TOTAL>>>(A4, x0, G);   // Y0 = W^T x0
    k_ap<1><<<G, 256, SM_TOTAL>>>(A4, x0, G);   // z1, Y1
    k_ap<2><<<G, 256, SM_TOTAL>>>(A4, x0, G);   // z2, Y2
    k_ap<3><<<G, 256, SM_TOTAL>>>(A4, x0, G);   // z3, Y3
    k_ap<4><<<G, 256, SM_TOTAL>>>(A4, x0, G);   // z4 -> u4, Y4
    k_ap<5><<<G, 256, SM_TOTAL>>>(A4, x0, G);   // largest in-kernel; ||w||^2, Y5

    k_pensum<<<BN, 32>>>(out);                  // penalty + final sum
}

// round 17
// speedup vs baseline: 1.2910x; 1.2910x over previous
#include <cuda_runtime.h>
#include <math.h>
#include <stdint.h>

#define BN 64
#define CN 512
#define HW 784
#define HW4 196
#define R_TOT (BN * CN)
#define FEPS 1e-12f

#define ROWB 3136                  // bytes per A row
#define DEPTH 3                    // cp.async stages per warp
#define SM_PIPE (8 * DEPTH * ROWB) // 75264
#define SM_YW   (SM_PIPE)          // yw: 8*784 floats at this offset
#define SM_R1S  (SM_PIPE + 8 * HW * 4)
#define SM_TOTAL (SM_R1S + 32)

// ---------------- scratch (static __device__, no allocation) ----------------
__device__ __align__(16) float g_Y[6][BN * HW];  // summed W^T z per sweep
__device__ float g_u4[BN * CN];
__device__ float g_nrm[6][BN];            // 0:||x0||^2 1..4:||z_k||^2 5:||w||^2
__device__ float g_pen[BN];
__device__ int   g_pendone;

__device__ __forceinline__ uint32_t s2u(const void* p) {
    uint32_t a;
    asm("{.reg .u64 t; cvta.to.shared.u64 t, %1; cvt.u32.u64 %0, t;}" : "=r"(a) : "l"(p));
    return a;
}
// Plain cp.async (LDGSTS); the cache-hint form traps on sm_103a.
__device__ __forceinline__ void cpa16(uint32_t dst, const float4* src) {
    asm volatile("cp.async.cg.shared.global [%0], [%1], 16;"
                 :: "r"(dst), "l"(src) : "memory");
}
#define CPA_COMMIT() asm volatile("cp.async.commit_group;" ::: "memory")
#define CPA_WAIT2()  asm volatile("cp.async.wait_group 2;" ::: "memory")
#define CPA_WAIT0()  asm volatile("cp.async.wait_group 0;" ::: "memory")
__device__ __forceinline__ float ldcg(const float* p) {
    float v; asm volatile("ld.global.cg.f32 %0,[%1];" : "=f"(v) : "l"(p)); return v;
}

// ---------------- init: zero Y+accums, ||x0||^2 ----------------
__global__ void k_init0(const float* __restrict__ x0) {
    __shared__ float red[16];
    int b = blockIdx.x, t = threadIdx.x;       // 64 blocks x 512 threads
    for (int s = 0; s < 6; s++)
        for (int i = t; i < HW; i += 512) g_Y[s][b * HW + i] = 0.f;
    if (t < 6) g_nrm[t][b] = 0.0f;
    if (b == 0 && t == 0) g_pendone = 0;
    float v = x0[b * CN + t];
    float s = v * v;
    #pragma unroll
    for (int o = 16; o; o >>= 1) s += __shfl_xor_sync(0xffffffffu, s, o);
    if ((t & 31) == 0) red[t >> 5] = s;
    __syncthreads();
    if (t < 16) {
        s = red[t];
        #pragma unroll
        for (int o = 8; o; o >>= 1) s += __shfl_xor_sync(0xffffu, s, o);
        if (t == 0) g_nrm[0][b] = s;
    }
}

// ---------------- sweep kernel: cp.async-fed, balanced static partition -----
// SWEEP 0: z = x0[c] (axpy only)
// SWEEP 1..4: z = A_row . ys (ys = Y[S-1]*rsqrt(nrm[S-1])); ||z||^2 -> nrm[S];
//             SWEEP 4 stores z -> g_u4
// SWEEP 5: inv4/largest computed per-warp from Y4 (fixed lane order);
//          ys = Y4*inv4; w = z - largest*(u4*inv4); ||w||^2 -> nrm[5]
template<int SWEEP>
__global__ void __launch_bounds__(256, 2) k_ap(
        const float4* __restrict__ A4, const float* __restrict__ x0, int G)
{
    extern __shared__ char sm[];
    float* yw = (float*)(sm + SM_YW);
    float* r1s = (float*)(sm + SM_R1S);
    int t = threadIdx.x, warp = t >> 5, lane = t & 31;   // 256 threads
    bool k6 = (lane < 4);
    uint32_t pbase = s2u(sm) + warp * (DEPTH * ROWB) + lane * 16;
    const float4* pipe4 = (const float4*)(sm + warp * (DEPTH * ROWB));

    int rs = (int)((long long)blockIdx.x * R_TOT / G);
    int re = (int)((long long)(blockIdx.x + 1) * R_TOT / G);

    bool first = true;
    while (rs < re) {
        int b = rs >> 9;
        int cs = rs & (CN - 1);
        int ce = re - (b << 9); if (ce > CN) ce = CN;

        if (!first) __syncthreads();   // protect yw reuse across subranges
        first = false;

        // ---- ys in registers (28 floats/thread); sweep5 also largest ----
        float4 ysr[7];
        float largest = 0.f, inv4 = 1.f;
        if (SWEEP >= 1) {
            int ssrc = (SWEEP <= 4) ? SWEEP - 1 : 4;
            const float4* Ysrc = (const float4*)(&g_Y[ssrc][b * HW]);
            float sc = 1.0f / fmaxf(sqrtf(g_nrm[ssrc][b]), FEPS);
            if (SWEEP < 5) {
                #pragma unroll
                for (int k = 0; k < 6; k++) {
                    float4 y = __ldg(Ysrc + k * 32 + lane);
                    ysr[k] = make_float4(y.x * sc, y.y * sc, y.z * sc, y.w * sc);
                }
                if (k6) {
                    float4 y = __ldg(Ysrc + 192 + lane);
                    ysr[6] = make_float4(y.x * sc, y.y * sc, y.z * sc, y.w * sc);
                } else ysr[6] = make_float4(0.f, 0.f, 0.f, 0.f);
            } else {
                inv4 = sc;
                float s0 = 0.f, s1 = 0.f, s2 = 0.f, s3 = 0.f;
                #pragma unroll
                for (int k = 0; k < 6; k++) {
                    float4 y = __ldg(Ysrc + k * 32 + lane);
                    s0 += y.x * y.x; s1 += y.y * y.y;
                    s2 += y.z * y.z; s3 += y.w * y.w;
                    ysr[k] = make_float4(y.x * sc, y.y * sc, y.z * sc, y.w * sc);
                }
                if (k6) {
                    float4 y = __ldg(Ysrc + 192 + lane);
                    s0 += y.x * y.x; s1 += y.y * y.y;
                    s2 += y.z * y.z; s3 += y.w * y.w;
                    ysr[6] = make_float4(y.x * sc, y.y * sc, y.z * sc, y.w * sc);
                } else ysr[6] = make_float4(0.f, 0.f, 0.f, 0.f);
                float sq = (s0 + s1) + (s2 + s3);
                #pragma unroll
                for (int o = 16; o; o >>= 1) sq += __shfl_xor_sync(0xffffffffu, sq, o);
                largest = sq * inv4 * inv4;     // ||W^T x1||^2
            }
        }

        float4 acc[7];
        #pragma unroll
        for (int k = 0; k < 7; k++) acc[k] = make_float4(0.f, 0.f, 0.f, 0.f);
        float la1 = 0.f;

        // ---- per-warp cp.async pipeline over rows c = cs+warp, step 8 ----
        int c0 = cs + warp;
        #pragma unroll
        for (int d = 0; d < DEPTH; d++) {
            int c = c0 + d * 8;
            if (c < ce) {
                const float4* src = A4 + (size_t)(b * CN + c) * HW4;
                uint32_t dst = pbase + d * ROWB;
                #pragma unroll
                for (int k = 0; k < 6; k++) cpa16(dst + k * 512, src + k * 32 + lane);
                if (k6) cpa16(dst + 6 * 512, src + 192 + lane);
            }
            CPA_COMMIT();
        }

        int stage = 0;
        for (int c = c0; c < ce; c += 8) {
            CPA_WAIT2();   // oldest group (this row) complete
            const float4* Ar = pipe4 + stage * (ROWB / 16);
            float4 a[7];
            #pragma unroll
            for (int k = 0; k < 6; k++) a[k] = Ar[k * 32 + lane];
            a[6] = k6 ? Ar[192 + lane] : make_float4(0.f, 0.f, 0.f, 0.f);

            {
                int cn = c + DEPTH * 8;
                if (cn < ce) {
                    const float4* src = A4 + (size_t)(b * CN + cn) * HW4;
                    uint32_t dst = pbase + stage * ROWB;
                    #pragma unroll
                    for (int k = 0; k < 6; k++) cpa16(dst + k * 512, src + k * 32 + lane);
                    if (k6) cpa16(dst + 6 * 512, src + 192 + lane);
                }
                CPA_COMMIT();
            }

            float z;
            if (SWEEP == 0) {
                z = __ldg(&x0[b * CN + c]);
            } else {
                float d0 = 0.f, d1 = 0.f, d2 = 0.f, d3 = 0.f;
                #pragma unroll
                for (int k = 0; k < 7; k++) {
                    d0 += a[k].x * ysr[k].x; d1 += a[k].y * ysr[k].y;
                    d2 += a[k].z * ysr[k].z; d3 += a[k].w * ysr[k].w;
                }
                z = (d0 + d1) + (d2 + d3);
                #pragma unroll
                for (int o = 16; o; o >>= 1) z += __shfl_xor_sync(0xffffffffu, z, o);
            }
            #pragma unroll
            for (int k = 0; k < 7; k++) {
                acc[k].x += z * a[k].x; acc[k].y += z * a[k].y;
                acc[k].z += z * a[k].z; acc[k].w += z * a[k].w;
            }
            if (lane == 0) {
                if (SWEEP >= 1 && SWEEP <= 4) {
                    if (SWEEP == 4) g_u4[b * CN + c] = z;
                    la1 += z * z;
                } else if (SWEEP == 5) {
                    float wv = z - largest * (g_u4[b * CN + c] * inv4);
                    la1 += wv * wv;
                }
            }
            stage = (stage + 1 == DEPTH) ? 0 : stage + 1;
        }
        CPA_WAIT0();   // drain before stage memory reuse next subrange

        // ---- block-reduce warp accs -> atomicAdd into g_Y[SWEEP][b] ----
        {
            float4* yo = (float4*)(yw + warp * HW);
            #pragma unroll
            for (int k = 0; k < 6; k++) yo[k * 32 + lane] = acc[k];
            if (k6) yo[192 + lane] = acc[6];
            if (lane == 0) r1s[warp] = la1;
        }
        __syncthreads();
        {
            float* Yp = &g_Y[SWEEP][b * HW];
            for (int i = t; i < HW; i += 256) {
                float s = 0.f;
                #pragma unroll
                for (int w = 0; w < 8; w++) s += yw[w * HW + i];
                atomicAdd(&Yp[i], s);
            }
        }
        if (t == 0 && SWEEP >= 1) {
            float s1 = 0.f;
            #pragma unroll
            for (int w = 0; w < 8; w++) s1 += r1s[w];
            atomicAdd(&g_nrm[SWEEP][b], s1);
        }
        rs = (b << 9) + ce;
    }
}

// ---------------- pen+sum: per-batch penalty; last block sums ----------------
__global__ void k_pensum(float* __restrict__ out) {
    __shared__ int is_last;
    int b = blockIdx.x, t = threadIdx.x, lane = t & 31;   // 64 blocks x 32 thr
    bool k6 = (lane < 4);
    // largest from Y4 in the SAME warp-lane order as k_ap<5>
    const float4* Y4 = (const float4*)(&g_Y[4][b * HW]);
    const float4* Y5 = (const float4*)(&g_Y[5][b * HW]);
    float inv4 = 1.0f / fmaxf(sqrtf(g_nrm[4][b]), FEPS);
    float s0 = 0.f, s1 = 0.f, s2 = 0.f, s3 = 0.f;
    float4 y4r[7];
    #pragma unroll
    for (int k = 0; k < 6; k++) {
        float4 y = __ldg(Y4 + k * 32 + lane);
        s0 += y.x * y.x; s1 += y.y * y.y;
        s2 += y.z * y.z; s3 += y.w * y.w;
        y4r[k] = y;
    }
    if (k6) {
        float4 y = __ldg(Y4 + 192 + lane);
        s0 += y.x * y.x; s1 += y.y * y.y;
        s2 += y.z * y.z; s3 += y.w * y.w;
        y4r[6] = y;
    } else y4r[6] = make_float4(0.f, 0.f, 0.f, 0.f);
    float sq = (s0 + s1) + (s2 + s3);
    #pragma unroll
    for (int o = 16; o; o >>= 1) sq += __shfl_xor_sync(0xffffffffu, sq, o);
    float largest = sq * inv4 * inv4;
    float f = largest * inv4;
    // num6 = || Y5 - f*Y4 ||^2
    float n0 = 0.f, n1 = 0.f, n2 = 0.f, n3 = 0.f;
    #pragma unroll
    for (int k = 0; k < 6; k++) {
        float4 y5 = __ldg(Y5 + k * 32 + lane);
        float ex = y5.x - f * y4r[k].x, ey = y5.y - f * y4r[k].y;
        float ez = y5.z - f * y4r[k].z, ew = y5.w - f * y4r[k].w;
        n0 += ex * ex; n1 += ey * ey; n2 += ez * ez; n3 += ew * ew;
    }
    if (k6) {
        float4 y5 = __ldg(Y5 + 192 + lane);
        float ex = y5.x - f * y4r[6].x, ey = y5.y - f * y4r[6].y;
        float ez = y5.z - f * y4r[6].z, ew = y5.w - f * y4r[6].w;
        n0 += ex * ex; n1 += ey * ey; n2 += ez * ez; n3 += ew * ew;
    }
    float num6 = (n0 + n1) + (n2 + n3);
    #pragma unroll
    for (int o = 16; o; o >>= 1) num6 += __shfl_xor_sync(0xffffffffu, num6, o);
    if (t == 0) {
        float smallest = num6 / g_nrm[5][b];     // ||W^T w||^2 / ||w||^2
        float r = largest / smallest - 1.0f;
        g_pen[b] = r * r;
        __threadfence();
        int done = atomicAdd(&g_pendone, 1);
        is_last = (done == BN - 1);
    }
    __syncwarp();
    if (is_last) {   // this block arrived last: all g_pen visible
        float p = ldcg(&g_pen[lane]) + ldcg(&g_pen[lane + 32]);
        #pragma unroll
        for (int o = 16; o; o >>= 1) p += __shfl_xor_sync(0xffffffffu, p, o);
        if (t == 0) out[0] = p / (float)BN;
    }
}

// ---------------- launch ----------------
extern "C" void kernel_launch(void* const* d_in, const int* in_sizes, int n_in,
                              void* d_out, int out_size) {
    const float* A  = (const float*)d_in[0];
    const float* x0 = (const float*)d_in[1];
    if (n_in >= 2 && in_sizes[0] < in_sizes[1]) {   // safety: A is the big one
        const float* t = A; A = x0; x0 = t;
    }
    const float4* A4 = (const float4*)A;
    float* out = (float*)d_out;
    (void)out_size;

    cudaFuncSetAttribute(k_ap<0>, cudaFuncAttributeMaxDynamicSharedMemorySize, SM_TOTAL);
    cudaFuncSetAttribute(k_ap<1>, cudaFuncAttributeMaxDynamicSharedMemorySize, SM_TOTAL);
    cudaFuncSetAttribute(k_ap<2>, cudaFuncAttributeMaxDynamicSharedMemorySize, SM_TOTAL);
    cudaFuncSetAttribute(k_ap<3>, cudaFuncAttributeMaxDynamicSharedMemorySize, SM_TOTAL);
    cudaFuncSetAttribute(k_ap<4>, cudaFuncAttributeMaxDynamicSharedMemorySize, SM_TOTAL);
    cudaFuncSetAttribute(k_ap<5>, cudaFuncAttributeMaxDynamicSharedMemorySize, SM_TOTAL);

    int nsm = 148;
    cudaDeviceGetAttribute(&nsm, cudaDevAttrMultiProcessorCount, 0);
    int G = nsm * 2;                         // exactly-resident balanced grid

    k_init0<<<BN, 512>>>(x0);

    k_ap<0><<<G, 256, SM_TOTAL>>>(A4, x0, G);   // Y0 = W^T x0
    k_ap<1><<<G, 256, SM_TOTAL>>>(A4, x0, G);   // z1, Y1
    k_ap<2><<<G, 256, SM_TOTAL>>>(A4, x0, G);   // z2, Y2
    k_ap<3><<<G, 256, SM_TOTAL>>>(A4, x0, G);   // z3, Y3
    k_ap<4><<<G, 256, SM_TOTAL>>>(A4, x0, G);   // z4 -> u4, Y4
    k_ap<5><<<G, 256, SM_TOTAL>>>(A4, x0, G);   // largest in-kernel; ||w||^2, Y5

    k_pensum<<<BN, 32>>>(out);                  // penalty + final sum
}